// round 11
// baseline (speedup 1.0000x reference)
#include <cuda_runtime.h>
#include <cuda_bf16.h>
#include <math.h>
#include <stdint.h>

// Problem constants
#define S_LEN 2048
#define BATCH 2
#define EMB   2048
#define HEADS 32
#define HDIM  64
#define MROWS (S_LEN * BATCH)          // 4096
#define QKV_N (3 * EMB)                // 6144
#define K3    6144                     // expanded K: [hi | lo | hi]
#define NIT   96                       // K3 / 64
#define MASK_NEG (-66504.0f)

// ---------------------------------------------------------------------------
// Scratch (static device globals)
// ---------------------------------------------------------------------------
__device__ float g_qkv[(size_t)MROWS * QKV_N];                 // [4096, 6144]
__device__ float g_ctx[(size_t)MROWS * EMB];                   // [4096, 2048]

__device__ __nv_bfloat16 g_A3 [(size_t)MROWS * K3];            // activations (hi|lo|hi)
__device__ __nv_bfloat16 g_B3q[(size_t)QKV_N * K3];            // qkv_w^T   (hi|hi|lo)
__device__ __nv_bfloat16 g_B3o[(size_t)EMB   * K3];            // out_w^T   (hi|hi|lo)

#define QKVLEN ((size_t)BATCH * HEADS * S_LEN * HDIM)
__device__ __nv_bfloat16 g_qb [QKVLEN];   // rope(Q) * 0.125, bf16
__device__ __nv_bfloat16 g_kb [QKVLEN];   // rope(K), bf16
__device__ __nv_bfloat16 g_vhb[QKVLEN];   // V hi
__device__ __nv_bfloat16 g_vlb[QKVLEN];   // V lo

// ---------------------------------------------------------------------------
// Helpers (sm_80-era PTX — legal at compute_103)
// ---------------------------------------------------------------------------
__device__ __forceinline__ uint32_t smem_u32(const void* p) {
    uint32_t a;
    asm("{ .reg .u64 t; cvta.to.shared.u64 t, %1; cvt.u32.u64 %0, t; }" : "=r"(a) : "l"(p));
    return a;
}
__device__ __forceinline__ void cp16(uint32_t saddr, const void* g) {
    asm volatile("cp.async.cg.shared.global [%0], [%1], 16;" :: "r"(saddr), "l"(g) : "memory");
}
__device__ __forceinline__ void cp_commit() {
    asm volatile("cp.async.commit_group;" ::: "memory");
}
__device__ __forceinline__ uint32_t sw128(uint32_t off) {
    return off ^ ((off >> 3) & 0x70);
}

#define LDSM4(r, addr) \
    asm volatile("ldmatrix.sync.aligned.m8n8.x4.shared.b16 {%0,%1,%2,%3}, [%4];" \
                 : "=r"((r)[0]), "=r"((r)[1]), "=r"((r)[2]), "=r"((r)[3]) : "r"(addr))

#define LDSM4T(r, addr) \
    asm volatile("ldmatrix.sync.aligned.m8n8.x4.trans.shared.b16 {%0,%1,%2,%3}, [%4];" \
                 : "=r"((r)[0]), "=r"((r)[1]), "=r"((r)[2]), "=r"((r)[3]) : "r"(addr))

__device__ __forceinline__ void mma_bf16(float* d, const uint32_t* a, uint32_t b0, uint32_t b1) {
    asm volatile(
        "mma.sync.aligned.m16n8k16.row.col.f32.bf16.bf16.f32 "
        "{%0,%1,%2,%3}, {%4,%5,%6,%7}, {%8,%9}, {%0,%1,%2,%3};"
        : "+f"(d[0]), "+f"(d[1]), "+f"(d[2]), "+f"(d[3])
        : "r"(a[0]), "r"(a[1]), "r"(a[2]), "r"(a[3]), "r"(b0), "r"(b1));
}

__device__ __forceinline__ uint32_t packlo(float a, float b, float& ra, float& rb) {
    __nv_bfloat162 h = __floats2bfloat162_rn(a, b);
    ra = a - __bfloat162float(__low2bfloat16(h));
    rb = b - __bfloat162float(__high2bfloat16(h));
    return *reinterpret_cast<uint32_t*>(&h);
}
__device__ __forceinline__ uint32_t packb(float a, float b) {
    __nv_bfloat162 h = __floats2bfloat162_rn(a, b);
    return *reinterpret_cast<uint32_t*>(&h);
}

// ---------------------------------------------------------------------------
// HMMA split-bf16 GEMM v4:  C[M=4096, N] = A3[M, K3] @ B3[N, K3]^T + bias
// CTA tile 128x128, BK=64, 3-stage cp.async, BUT only 4 warps (2x2), each
// owning a 64x64 warp tile. 128 threads/CTA, 2 CTAs/SM -> 256 regs/thread
// available (acc 128 + frags fit without spills). Per warp-k16: 8 LDSM4
// feed 32 MMAs (2x the MMA:LDSM ratio of the 8-warp version), smem port
// load drops from ~100% to ~75% of tensor-pipe time.
// ---------------------------------------------------------------------------
#define GEMM_SMEM (3 * 32768)

__global__ __launch_bounds__(128, 2)
void gemm_mma_bf16(int N,
                   const __nv_bfloat16* __restrict__ A3,
                   const __nv_bfloat16* __restrict__ B3,
                   const float* __restrict__ bias,
                   float* __restrict__ C) {
    extern __shared__ char sm[];
    const int tid = threadIdx.x;
    const int wid = tid >> 5;
    const int lid = tid & 31;
    const int M0 = blockIdx.y * 128;
    const int N0 = blockIdx.x * 128;
    const uint32_t sbase = smem_u32(sm);

    // loader: one 128B row per thread for A and for B (8 cp16 each)
    const uint32_t soff = (uint32_t)tid * 128u;
    const char* Ag = (const char*)(A3 + (size_t)(M0 + tid) * K3);
    const char* Bg = (const char*)(B3 + (size_t)(N0 + tid) * K3);

    // warp tiling: 2x2, each warp 64x64
    const int wm = (wid & 1) * 64;
    const int wn = (wid >> 1) * 64;
    const int a_r  = wm + (lid & 15);
    const int a_cb = (lid >> 4) * 16;
    const int b_r  = wn + (lid & 7) + ((lid >> 4) << 3);
    const int b_cb = ((lid >> 3) & 1) * 16;

    float acc[4][8][4];
#pragma unroll
    for (int i = 0; i < 4; ++i)
#pragma unroll
        for (int j = 0; j < 8; ++j)
#pragma unroll
            for (int q = 0; q < 4; ++q) acc[i][j][q] = 0.0f;

    // prologue: stages 0,1
#pragma unroll
    for (int s = 0; s < 2; ++s) {
        uint32_t ab = sbase + s * 32768u;
        uint32_t bb = ab + 16384u;
        const char* ag = Ag + s * 128;
        const char* bg = Bg + s * 128;
#pragma unroll
        for (int i = 0; i < 8; ++i) {
            cp16(ab + sw128(soff + i * 16), ag + i * 16);
            cp16(bb + sw128(soff + i * 16), bg + i * 16);
        }
        cp_commit();
    }

#pragma unroll 1
    for (int it = 0; it < NIT; ++it) {
        if (it + 1 < NIT) asm volatile("cp.async.wait_group 1;" ::: "memory");
        else              asm volatile("cp.async.wait_group 0;" ::: "memory");
        __syncthreads();

        if (it + 2 < NIT) {
            int s1 = (it + 2) % 3;
            uint32_t ab = sbase + s1 * 32768u;
            uint32_t bb = ab + 16384u;
            const char* ag = Ag + (size_t)(it + 2) * 128;
            const char* bg = Bg + (size_t)(it + 2) * 128;
#pragma unroll
            for (int i = 0; i < 8; ++i) {
                cp16(ab + sw128(soff + i * 16), ag + i * 16);
                cp16(bb + sw128(soff + i * 16), bg + i * 16);
            }
            cp_commit();
        }

        const int s = it % 3;
        const uint32_t ab = sbase + s * 32768u;
        const uint32_t bb = ab + 16384u;

#pragma unroll
        for (int kk = 0; kk < 4; ++kk) {
            uint32_t Ar[4][4];
            uint32_t Br[4][4];
#pragma unroll
            for (int i = 0; i < 4; ++i)
                LDSM4(Ar[i], ab + sw128((uint32_t)(a_r + i * 16) * 128u + kk * 32 + a_cb));
#pragma unroll
            for (int j2 = 0; j2 < 4; ++j2)
                LDSM4(Br[j2], bb + sw128((uint32_t)(b_r + j2 * 16) * 128u + kk * 32 + b_cb));
#pragma unroll
            for (int i = 0; i < 4; ++i)
#pragma unroll
                for (int j = 0; j < 8; ++j)
                    mma_bf16(acc[i][j], Ar[i], Br[j >> 1][(j & 1) * 2], Br[j >> 1][(j & 1) * 2 + 1]);
        }
    }

    // epilogue: m16n8 fragment -> rows (lid>>2, +8), cols (lid&3)*2
    const int fr = lid >> 2;
    const int fc = (lid & 3) * 2;
#pragma unroll
    for (int j = 0; j < 8; ++j) {
        const int col = N0 + wn + j * 8 + fc;
        const float bx = bias[col];
        const float by = bias[col + 1];
#pragma unroll
        for (int i = 0; i < 4; ++i) {
            const int row = M0 + wm + i * 16 + fr;
            float2 v0 = make_float2(acc[i][j][0] + bx, acc[i][j][1] + by);
            float2 v1 = make_float2(acc[i][j][2] + bx, acc[i][j][3] + by);
            *reinterpret_cast<float2*>(C + (size_t)row * N + col) = v0;
            *reinterpret_cast<float2*>(C + (size_t)(row + 8) * N + col) = v1;
        }
    }
}

// ---------------------------------------------------------------------------
// Conversions (unchanged)
// ---------------------------------------------------------------------------
__global__ __launch_bounds__(256)
void convA_kernel(const float* __restrict__ src, __nv_bfloat16* __restrict__ dst) {
    int i = blockIdx.x * 256 + threadIdx.x;
    int m = i >> 9;
    int j = (i & 511) * 4;
    float4 a = *reinterpret_cast<const float4*>(src + (size_t)m * EMB + j);
    float v[4] = {a.x, a.y, a.z, a.w};
    __nv_bfloat16 h[4], l[4];
#pragma unroll
    for (int q = 0; q < 4; ++q) {
        h[q] = __float2bfloat16(v[q]);
        l[q] = __float2bfloat16(v[q] - __bfloat162float(h[q]));
    }
    __nv_bfloat16* d0 = dst + (size_t)m * K3 + j;
    __nv_bfloat162 h01 = __halves2bfloat162(h[0], h[1]);
    __nv_bfloat162 h23 = __halves2bfloat162(h[2], h[3]);
    __nv_bfloat162 l01 = __halves2bfloat162(l[0], l[1]);
    __nv_bfloat162 l23 = __halves2bfloat162(l[2], l[3]);
    *reinterpret_cast<__nv_bfloat162*>(d0 + 0) = h01;
    *reinterpret_cast<__nv_bfloat162*>(d0 + 2) = h23;
    *reinterpret_cast<__nv_bfloat162*>(d0 + 2048 + 0) = l01;
    *reinterpret_cast<__nv_bfloat162*>(d0 + 2048 + 2) = l23;
    *reinterpret_cast<__nv_bfloat162*>(d0 + 4096 + 0) = h01;
    *reinterpret_cast<__nv_bfloat162*>(d0 + 4096 + 2) = h23;
}

__global__ __launch_bounds__(1024)
void convB_kernel(const float* __restrict__ src, __nv_bfloat16* __restrict__ dst, int Ncols) {
    __shared__ float tile[32][33];
    const int k0 = blockIdx.y * 32;
    const int n0 = blockIdx.x * 32;
    const int tx = threadIdx.x;
    const int ty = threadIdx.y;
    tile[ty][tx] = src[(size_t)(k0 + ty) * Ncols + n0 + tx];
    __syncthreads();
    float v = tile[tx][ty];
    __nv_bfloat16 h = __float2bfloat16(v);
    __nv_bfloat16 lo = __float2bfloat16(v - __bfloat162float(h));
    size_t drow = (size_t)(n0 + ty) * K3 + k0 + tx;
    dst[drow + 0]    = h;
    dst[drow + 2048] = h;
    dst[drow + 4096] = lo;
}

// ---------------------------------------------------------------------------
// RoPE + split -> bf16 Q (pre-scaled by 0.125), K, Vh, Vl
// ---------------------------------------------------------------------------
__global__ __launch_bounds__(256)
void rope_split_kernel() {
    int idx = blockIdx.x * blockDim.x + threadIdx.x;
    int d = idx & 63;
    int h = (idx >> 6) & 31;
    int b = (idx >> 11) & 1;
    int s = idx >> 12;

    const float* base = g_qkv + (size_t)(s * BATCH + b) * QKV_N;
    int col = h * HDIM + d;

    float qv = base[col];
    float kv = base[EMB + col];
    float vv = base[2 * EMB + col];

    int i = d & 31;
    float inv_freq = __expf(-0.28782252f * (float)i);
    float ang = (float)s * inv_freq;
    float sn, cs;
    sincosf(ang, &sn, &cs);

    float qpair, kpair;
    if (d < 32) {
        qpair = -base[col + 32];
        kpair = -base[EMB + col + 32];
    } else {
        qpair = base[col - 32];
        kpair = base[EMB + col - 32];
    }

    float qr = qv * cs + qpair * sn;
    float kr = kv * cs + kpair * sn;

    size_t o = ((size_t)(b * HEADS + h) * S_LEN + s) * HDIM + d;
    g_qb[o] = __float2bfloat16(qr * 0.125f);
    g_kb[o] = __float2bfloat16(kr);
    __nv_bfloat16 vh = __float2bfloat16(vv);
    g_vhb[o] = vh;
    g_vlb[o] = __float2bfloat16(vv - __bfloat162float(vh));
}

// ---------------------------------------------------------------------------
// HMMA flash attention (unchanged from round 10 — the new win)
// ---------------------------------------------------------------------------
#define ATTN_SMEM 65536

__global__ __launch_bounds__(256, 2)
void attn_kernel() {
    extern __shared__ char smc[];
    const uint32_t sQ = smem_u32(smc);

    const int bh = blockIdx.y;
    const int qt = 15 - (int)blockIdx.x;
    const int q0 = qt * 128;
    const int t  = threadIdx.x;
    const int w  = t >> 5;
    const int lid = t & 31;

    const __nv_bfloat16* Qg  = g_qb  + (size_t)bh * S_LEN * HDIM;
    const __nv_bfloat16* Kg  = g_kb  + (size_t)bh * S_LEN * HDIM;
    const __nv_bfloat16* Vhg = g_vhb + (size_t)bh * S_LEN * HDIM;
    const __nv_bfloat16* Vlg = g_vlb + (size_t)bh * S_LEN * HDIM;

    {
        const int row = t >> 1;
        const int half = (t & 1) * 64;
        const char* src = (const char*)(Qg + (size_t)(q0 + row) * HDIM) + half;
#pragma unroll
        for (int i = 0; i < 4; ++i)
            cp16(sQ + sw128((uint32_t)row * 128u + half + i * 16), src + i * 16);
    }
    {
        const int row = t >> 2;
        const int qo = (t & 3) * 32;
        const uint32_t so = sw128((uint32_t)row * 128u + qo);
        const uint32_t so2 = sw128((uint32_t)row * 128u + qo + 16);
        const char* kg = (const char*)(Kg + (size_t)row * HDIM) + qo;
        const char* vh = (const char*)(Vhg + (size_t)row * HDIM) + qo;
        const char* vl = (const char*)(Vlg + (size_t)row * HDIM) + qo;
        uint32_t bK = sQ + 16384u;
        cp16(bK + so, kg);           cp16(bK + so2, kg + 16);
        cp16(bK + 8192u + so, vh);   cp16(bK + 8192u + so2, vh + 16);
        cp16(bK + 16384u + so, vl);  cp16(bK + 16384u + so2, vl + 16);
    }
    cp_commit();

    float oc[8][4];
#pragma unroll
    for (int jn = 0; jn < 8; ++jn)
#pragma unroll
        for (int q = 0; q < 4; ++q) oc[jn][q] = 0.0f;
    float m[2] = {-1e30f, -1e30f};
    float l[2] = {0.0f, 0.0f};

    const int nkt = 2 * qt + 2;
#pragma unroll 1
    for (int kt = 0; kt < nkt; ++kt) {
        if (kt + 1 < nkt) {
            const int k1 = (kt + 1) * 64;
            const int row = t >> 2;
            const int qo = (t & 3) * 32;
            const uint32_t so = sw128((uint32_t)row * 128u + qo);
            const uint32_t so2 = sw128((uint32_t)row * 128u + qo + 16);
            const char* kg = (const char*)(Kg + (size_t)(k1 + row) * HDIM) + qo;
            const char* vh = (const char*)(Vhg + (size_t)(k1 + row) * HDIM) + qo;
            const char* vl = (const char*)(Vlg + (size_t)(k1 + row) * HDIM) + qo;
            uint32_t bK = sQ + 16384u + ((kt + 1) & 1) * 24576u;
            cp16(bK + so, kg);           cp16(bK + so2, kg + 16);
            cp16(bK + 8192u + so, vh);   cp16(bK + 8192u + so2, vh + 16);
            cp16(bK + 16384u + so, vl);  cp16(bK + 16384u + so2, vl + 16);
            cp_commit();
            asm volatile("cp.async.wait_group 1;" ::: "memory");
        } else {
            asm volatile("cp.async.wait_group 0;" ::: "memory");
        }
        __syncthreads();

        const uint32_t bK  = sQ + 16384u + (kt & 1) * 24576u;
        const uint32_t bVh = bK + 8192u;
        const uint32_t bVl = bK + 16384u;
        const int k0 = kt * 64;

        float sc[8][4];
#pragma unroll
        for (int jn = 0; jn < 8; ++jn)
#pragma unroll
            for (int q = 0; q < 4; ++q) sc[jn][q] = 0.0f;

#pragma unroll
        for (int k4 = 0; k4 < 4; ++k4) {
            uint32_t QA[4];
            LDSM4(QA, sQ + sw128((uint32_t)(w * 16 + (lid & 15)) * 128u + k4 * 32 + (lid >> 4) * 16));
#pragma unroll
            for (int j2 = 0; j2 < 4; ++j2) {
                uint32_t KB[4];
                LDSM4(KB, bK + sw128((uint32_t)((lid & 7) + ((lid >> 4) << 3) + j2 * 16) * 128u
                                     + k4 * 32 + ((lid >> 3) & 1) * 16));
                mma_bf16(sc[j2 * 2 + 0], QA, KB[0], KB[1]);
                mma_bf16(sc[j2 * 2 + 1], QA, KB[2], KB[3]);
            }
        }

        if (k0 + 63 > q0 + w * 16) {
            const int rlo = q0 + w * 16 + (lid >> 2);
#pragma unroll
            for (int jn = 0; jn < 8; ++jn) {
                const int cb = k0 + jn * 8 + (lid & 3) * 2;
#pragma unroll
                for (int q = 0; q < 4; ++q) {
                    const int colg = cb + (q & 1);
                    const int rowg = rlo + (q >> 1) * 8;
                    if (colg > rowg) sc[jn][q] += MASK_NEG;
                }
            }
        }

#pragma unroll
        for (int hh = 0; hh < 2; ++hh) {
            float mt = sc[0][hh * 2];
#pragma unroll
            for (int jn = 0; jn < 8; ++jn)
                mt = fmaxf(mt, fmaxf(sc[jn][hh * 2], sc[jn][hh * 2 + 1]));
            mt = fmaxf(mt, __shfl_xor_sync(0xffffffffu, mt, 1));
            mt = fmaxf(mt, __shfl_xor_sync(0xffffffffu, mt, 2));

            const float mn = fmaxf(m[hh], mt);
            const float corr = __expf(m[hh] - mn);
            float ps = 0.0f;
#pragma unroll
            for (int jn = 0; jn < 8; ++jn) {
                float p0 = __expf(sc[jn][hh * 2] - mn);
                float p1 = __expf(sc[jn][hh * 2 + 1] - mn);
                sc[jn][hh * 2] = p0;
                sc[jn][hh * 2 + 1] = p1;
                ps += p0 + p1;
            }
            ps += __shfl_xor_sync(0xffffffffu, ps, 1);
            ps += __shfl_xor_sync(0xffffffffu, ps, 2);
            l[hh] = l[hh] * corr + ps;
            m[hh] = mn;
#pragma unroll
            for (int jn = 0; jn < 8; ++jn) {
                oc[jn][hh * 2] *= corr;
                oc[jn][hh * 2 + 1] *= corr;
            }
        }

#pragma unroll
        for (int k4 = 0; k4 < 4; ++k4) {
            uint32_t PhA[4], PlA[4];
            {
                float r0, r1, r2, r3, r4, r5, r6, r7;
                PhA[0] = packlo(sc[2 * k4][0], sc[2 * k4][1], r0, r1);
                PhA[1] = packlo(sc[2 * k4][2], sc[2 * k4][3], r2, r3);
                PhA[2] = packlo(sc[2 * k4 + 1][0], sc[2 * k4 + 1][1], r4, r5);
                PhA[3] = packlo(sc[2 * k4 + 1][2], sc[2 * k4 + 1][3], r6, r7);
                PlA[0] = packb(r0, r1);
                PlA[1] = packb(r2, r3);
                PlA[2] = packb(r4, r5);
                PlA[3] = packb(r6, r7);
            }
#pragma unroll
            for (int j2 = 0; j2 < 4; ++j2) {
                uint32_t VhB[4], VlB[4];
                LDSM4T(VhB, bVh + sw128((uint32_t)(k4 * 16 + (lid & 15)) * 128u + j2 * 32 + (lid >> 4) * 16));
                LDSM4T(VlB, bVl + sw128((uint32_t)(k4 * 16 + (lid & 15)) * 128u + j2 * 32 + (lid >> 4) * 16));
                mma_bf16(oc[j2 * 2 + 0], PhA, VhB[0], VhB[1]);
                mma_bf16(oc[j2 * 2 + 1], PhA, VhB[2], VhB[3]);
                mma_bf16(oc[j2 * 2 + 0], PhA, VlB[0], VlB[1]);
                mma_bf16(oc[j2 * 2 + 1], PhA, VlB[2], VlB[3]);
                mma_bf16(oc[j2 * 2 + 0], PlA, VhB[0], VhB[1]);
                mma_bf16(oc[j2 * 2 + 1], PlA, VhB[2], VhB[3]);
            }
        }
        __syncthreads();
    }

    const int b = bh >> 5;
    const int h = bh & 31;
#pragma unroll
    for (int hh = 0; hh < 2; ++hh) {
        const int row = q0 + w * 16 + (lid >> 2) + hh * 8;
        const float invl = 1.0f / l[hh];
        float* dst = g_ctx + (size_t)(row * BATCH + b) * EMB + h * HDIM;
#pragma unroll
        for (int jn = 0; jn < 8; ++jn) {
            float2 v = make_float2(oc[jn][hh * 2] * invl, oc[jn][hh * 2 + 1] * invl);
            *reinterpret_cast<float2*>(dst + jn * 8 + (lid & 3) * 2) = v;
        }
    }
}

// ---------------------------------------------------------------------------
// Launch
// ---------------------------------------------------------------------------
extern "C" void kernel_launch(void* const* d_in, const int* in_sizes, int n_in,
                              void* d_out, int out_size) {
    const float* hs    = (const float*)d_in[0];
    const float* qkv_w = (const float*)d_in[1];
    const float* qkv_b = (const float*)d_in[2];
    const float* out_w = (const float*)d_in[3];
    const float* out_b = (const float*)d_in[4];
    float* out = (float*)d_out;

    cudaFuncSetAttribute(gemm_mma_bf16, cudaFuncAttributeMaxDynamicSharedMemorySize, GEMM_SMEM);
    cudaFuncSetAttribute(attn_kernel, cudaFuncAttributeMaxDynamicSharedMemorySize, ATTN_SMEM);

    float *qkv, *ctx;
    __nv_bfloat16 *A3, *B3q, *B3o;
    cudaGetSymbolAddress((void**)&qkv, g_qkv);
    cudaGetSymbolAddress((void**)&ctx, g_ctx);
    cudaGetSymbolAddress((void**)&A3,  g_A3);
    cudaGetSymbolAddress((void**)&B3q, g_B3q);
    cudaGetSymbolAddress((void**)&B3o, g_B3o);

    // Weight conversions (transpose + hi/lo split)
    {
        dim3 blk(32, 32);
        convB_kernel<<<dim3(QKV_N / 32, EMB / 32), blk>>>(qkv_w, B3q, QKV_N);
        convB_kernel<<<dim3(EMB / 32, EMB / 32), blk>>>(out_w, B3o, EMB);
    }
    convA_kernel<<<MROWS * 512 / 256, 256>>>(hs, A3);

    // 1. QKV projection (HMMA split-bf16, 4-warp 64x64 tiles)
    gemm_mma_bf16<<<dim3(QKV_N / 128, MROWS / 128), 128, GEMM_SMEM>>>(QKV_N, A3, B3q, qkv_b, qkv);

    // 2. RoPE + split -> bf16 Q/K/Vh/Vl
    rope_split_kernel<<<(S_LEN * BATCH * HEADS * HDIM) / 256, 256>>>();

    // 3. Causal attention (HMMA flash)
    attn_kernel<<<dim3(S_LEN / 128, BATCH * HEADS), 256, ATTN_SMEM>>>();

    // 4. ctx conversion + output projection
    convA_kernel<<<MROWS * 512 / 256, 256>>>(ctx, A3);
    gemm_mma_bf16<<<dim3(EMB / 128, MROWS / 128), 128, GEMM_SMEM>>>(EMB, A3, B3o, out_b, out);
}

// round 12
// speedup vs baseline: 1.7412x; 1.7412x over previous
#include <cuda_runtime.h>
#include <cuda_bf16.h>
#include <math.h>
#include <stdint.h>

// Problem constants
#define S_LEN 2048
#define BATCH 2
#define EMB   2048
#define HEADS 32
#define HDIM  64
#define MROWS (S_LEN * BATCH)          // 4096
#define QKV_N (3 * EMB)                // 6144
#define KDIM  2048
#define NIT_T 64                       // 2048 / 32 (BK=32 fp32)
#define MASK_NEG (-66504.0f)

// ---------------------------------------------------------------------------
// Scratch (static device globals)
// ---------------------------------------------------------------------------
__device__ float g_qkv[(size_t)MROWS * QKV_N];                 // [4096, 6144]
__device__ float g_ctx[(size_t)MROWS * EMB];                   // [4096, 2048]

__device__ float g_Btq[(size_t)QKV_N * KDIM];                  // qkv_w^T  [6144, 2048] fp32
__device__ float g_Bto[(size_t)EMB   * KDIM];                  // out_w^T  [2048, 2048] fp32

#define QKVLEN ((size_t)BATCH * HEADS * S_LEN * HDIM)
__device__ __nv_bfloat16 g_qb [QKVLEN];   // rope(Q) * 0.125, bf16
__device__ __nv_bfloat16 g_kb [QKVLEN];   // rope(K), bf16
__device__ __nv_bfloat16 g_vhb[QKVLEN];   // V hi
__device__ __nv_bfloat16 g_vlb[QKVLEN];   // V lo

// ---------------------------------------------------------------------------
// Helpers (sm_80-era PTX — legal at compute_103)
// ---------------------------------------------------------------------------
__device__ __forceinline__ uint32_t smem_u32(const void* p) {
    uint32_t a;
    asm("{ .reg .u64 t; cvta.to.shared.u64 t, %1; cvt.u32.u64 %0, t; }" : "=r"(a) : "l"(p));
    return a;
}
__device__ __forceinline__ void cp16(uint32_t saddr, const void* g) {
    asm volatile("cp.async.cg.shared.global [%0], [%1], 16;" :: "r"(saddr), "l"(g) : "memory");
}
__device__ __forceinline__ void cp_commit() {
    asm volatile("cp.async.commit_group;" ::: "memory");
}
__device__ __forceinline__ uint32_t sw128(uint32_t off) {
    return off ^ ((off >> 3) & 0x70);
}

#define LDSM4(r, addr) \
    asm volatile("ldmatrix.sync.aligned.m8n8.x4.shared.b16 {%0,%1,%2,%3}, [%4];" \
                 : "=r"((r)[0]), "=r"((r)[1]), "=r"((r)[2]), "=r"((r)[3]) : "r"(addr))

#define LDSM4T(r, addr) \
    asm volatile("ldmatrix.sync.aligned.m8n8.x4.trans.shared.b16 {%0,%1,%2,%3}, [%4];" \
                 : "=r"((r)[0]), "=r"((r)[1]), "=r"((r)[2]), "=r"((r)[3]) : "r"(addr))

__device__ __forceinline__ void mma_bf16(float* d, const uint32_t* a, uint32_t b0, uint32_t b1) {
    asm volatile(
        "mma.sync.aligned.m16n8k16.row.col.f32.bf16.bf16.f32 "
        "{%0,%1,%2,%3}, {%4,%5,%6,%7}, {%8,%9}, {%0,%1,%2,%3};"
        : "+f"(d[0]), "+f"(d[1]), "+f"(d[2]), "+f"(d[3])
        : "r"(a[0]), "r"(a[1]), "r"(a[2]), "r"(a[3]), "r"(b0), "r"(b1));
}

__device__ __forceinline__ void mma_tf32(float* d, const uint32_t* a, uint32_t b0, uint32_t b1) {
    asm volatile(
        "mma.sync.aligned.m16n8k8.row.col.f32.tf32.tf32.f32 "
        "{%0,%1,%2,%3}, {%4,%5,%6,%7}, {%8,%9}, {%0,%1,%2,%3};"
        : "+f"(d[0]), "+f"(d[1]), "+f"(d[2]), "+f"(d[3])
        : "r"(a[0]), "r"(a[1]), "r"(a[2]), "r"(a[3]), "r"(b0), "r"(b1));
}

__device__ __forceinline__ uint32_t packlo(float a, float b, float& ra, float& rb) {
    __nv_bfloat162 h = __floats2bfloat162_rn(a, b);
    ra = a - __bfloat162float(__low2bfloat16(h));
    rb = b - __bfloat162float(__high2bfloat16(h));
    return *reinterpret_cast<uint32_t*>(&h);
}
__device__ __forceinline__ uint32_t packb(float a, float b) {
    __nv_bfloat162 h = __floats2bfloat162_rn(a, b);
    return *reinterpret_cast<uint32_t*>(&h);
}

// ---------------------------------------------------------------------------
// TF32 HMMA GEMM:  C[M=4096, N] = A[M, 2048] @ Bt[N, 2048]^T + bias
// A, Bt raw fp32 (read as tf32 by the tensor core — 11-bit mantissa,
// rel err ~1e-4, no operand conversion passes needed).
// CTA tile 128x128, BK=32 (128B rows), 3-stage cp.async, 8 warps (2x4,
// 64x32 warp tile), 2 CTAs/SM — the proven R5/R10 schedule, 2/3 the slots.
// ldmatrix.x4 on 32-bit elements: A-frag addressing identical to bf16
// (row = lid&15, +16B half by lid>>4); B-frag pairs are {r0,r2},{r1,r3}.
// ---------------------------------------------------------------------------
#define GEMM_SMEM (3 * 32768)

__global__ __launch_bounds__(256, 2)
void gemm_mma_tf32(int N,
                   const float* __restrict__ A,
                   const float* __restrict__ Bt,
                   const float* __restrict__ bias,
                   float* __restrict__ C) {
    extern __shared__ char sm[];
    const int tid = threadIdx.x;
    const int wid = tid >> 5;
    const int lid = tid & 31;
    const int M0 = blockIdx.y * 128;
    const int N0 = blockIdx.x * 128;
    const uint32_t sbase = smem_u32(sm);

    // loader: 2 threads per 128B row-chunk (BK=32 fp32)
    const int lrow  = tid >> 1;
    const int lhalf = (tid & 1) * 64;
    const uint32_t soff = (uint32_t)lrow * 128u + (uint32_t)lhalf;
    const char* Ag = (const char*)(A  + (size_t)(M0 + lrow) * KDIM) + lhalf;
    const char* Bg = (const char*)(Bt + (size_t)(N0 + lrow) * KDIM) + lhalf;

    // warp tiling: wm in {0,64}, wn in {0,32,64,96}
    const int wm = (wid & 1) * 64;
    const int wn = (wid >> 1) * 32;
    const int a_r  = wm + (lid & 15);
    const int ldsm_cb = (lid >> 4) * 16;     // 16B half select (k0-3 vs k4-7)
    const int b_r  = wn + (lid & 15);

    float acc[4][4][4];
#pragma unroll
    for (int i = 0; i < 4; ++i)
#pragma unroll
        for (int j = 0; j < 4; ++j)
#pragma unroll
            for (int q = 0; q < 4; ++q) acc[i][j][q] = 0.0f;

    // prologue: stages 0,1
#pragma unroll
    for (int s = 0; s < 2; ++s) {
        uint32_t ab = sbase + s * 32768u;
        uint32_t bb = ab + 16384u;
        const char* ag = Ag + s * 128;
        const char* bg = Bg + s * 128;
#pragma unroll
        for (int i = 0; i < 4; ++i) {
            cp16(ab + sw128(soff + i * 16), ag + i * 16);
            cp16(bb + sw128(soff + i * 16), bg + i * 16);
        }
        cp_commit();
    }

#pragma unroll 1
    for (int it = 0; it < NIT_T; ++it) {
        if (it + 1 < NIT_T) asm volatile("cp.async.wait_group 1;" ::: "memory");
        else                asm volatile("cp.async.wait_group 0;" ::: "memory");
        __syncthreads();

        if (it + 2 < NIT_T) {
            int s1 = (it + 2) % 3;
            uint32_t ab = sbase + s1 * 32768u;
            uint32_t bb = ab + 16384u;
            const char* ag = Ag + (size_t)(it + 2) * 128;
            const char* bg = Bg + (size_t)(it + 2) * 128;
#pragma unroll
            for (int i = 0; i < 4; ++i) {
                cp16(ab + sw128(soff + i * 16), ag + i * 16);
                cp16(bb + sw128(soff + i * 16), bg + i * 16);
            }
            cp_commit();
        }

        const int s = it % 3;
        const uint32_t ab = sbase + s * 32768u;
        const uint32_t bb = ab + 16384u;

        // 4 k8 slices per BK=32 stage (k8 slice = 32 bytes)
#pragma unroll
        for (int k8 = 0; k8 < 4; ++k8) {
            uint32_t Ar[4][4];
            uint32_t Br[2][4];
#pragma unroll
            for (int i = 0; i < 4; ++i)
                LDSM4(Ar[i], ab + sw128((uint32_t)(a_r + i * 16) * 128u + k8 * 32 + ldsm_cb));
#pragma unroll
            for (int j2 = 0; j2 < 2; ++j2)
                LDSM4(Br[j2], bb + sw128((uint32_t)(b_r + j2 * 16) * 128u + k8 * 32 + ldsm_cb));
#pragma unroll
            for (int i = 0; i < 4; ++i)
#pragma unroll
                for (int j = 0; j < 4; ++j)
                    mma_tf32(acc[i][j], Ar[i],
                             Br[j >> 1][(j & 1)], Br[j >> 1][(j & 1) + 2]);
        }
    }

    // epilogue: m16n8 fragment -> rows (lid>>2, +8), cols (lid&3)*2
    const int fr = lid >> 2;
    const int fc = (lid & 3) * 2;
#pragma unroll
    for (int j = 0; j < 4; ++j) {
        const int col = N0 + wn + j * 8 + fc;
        const float bx = bias[col];
        const float by = bias[col + 1];
#pragma unroll
        for (int i = 0; i < 4; ++i) {
            const int row = M0 + wm + i * 16 + fr;
            float2 v0 = make_float2(acc[i][j][0] + bx, acc[i][j][1] + by);
            float2 v1 = make_float2(acc[i][j][2] + bx, acc[i][j][3] + by);
            *reinterpret_cast<float2*>(C + (size_t)row * N + col) = v0;
            *reinterpret_cast<float2*>(C + (size_t)(row + 8) * N + col) = v1;
        }
    }
}

// ---------------------------------------------------------------------------
// Weight transpose: fp32 [2048, Ncols] -> [Ncols, 2048]
// ---------------------------------------------------------------------------
__global__ __launch_bounds__(1024)
void transpose_kernel(const float* __restrict__ src, float* __restrict__ dst, int Ncols) {
    __shared__ float tile[32][33];
    const int k0 = blockIdx.y * 32;
    const int n0 = blockIdx.x * 32;
    const int tx = threadIdx.x;
    const int ty = threadIdx.y;
    tile[ty][tx] = src[(size_t)(k0 + ty) * Ncols + n0 + tx];
    __syncthreads();
    dst[(size_t)(n0 + ty) * KDIM + k0 + tx] = tile[tx][ty];
}

// ---------------------------------------------------------------------------
// RoPE + split -> bf16 Q (pre-scaled by 0.125), K, Vh, Vl  (unchanged)
// ---------------------------------------------------------------------------
__global__ __launch_bounds__(256)
void rope_split_kernel() {
    int idx = blockIdx.x * blockDim.x + threadIdx.x;
    int d = idx & 63;
    int h = (idx >> 6) & 31;
    int b = (idx >> 11) & 1;
    int s = idx >> 12;

    const float* base = g_qkv + (size_t)(s * BATCH + b) * QKV_N;
    int col = h * HDIM + d;

    float qv = base[col];
    float kv = base[EMB + col];
    float vv = base[2 * EMB + col];

    int i = d & 31;
    float inv_freq = __expf(-0.28782252f * (float)i);
    float ang = (float)s * inv_freq;
    float sn, cs;
    sincosf(ang, &sn, &cs);

    float qpair, kpair;
    if (d < 32) {
        qpair = -base[col + 32];
        kpair = -base[EMB + col + 32];
    } else {
        qpair = base[col - 32];
        kpair = base[EMB + col - 32];
    }

    float qr = qv * cs + qpair * sn;
    float kr = kv * cs + kpair * sn;

    size_t o = ((size_t)(b * HEADS + h) * S_LEN + s) * HDIM + d;
    g_qb[o] = __float2bfloat16(qr * 0.125f);
    g_kb[o] = __float2bfloat16(kr);
    __nv_bfloat16 vh = __float2bfloat16(vv);
    g_vhb[o] = vh;
    g_vlb[o] = __float2bfloat16(vv - __bfloat162float(vh));
}

// ---------------------------------------------------------------------------
// HMMA flash attention (unchanged from round 10)
// ---------------------------------------------------------------------------
#define ATTN_SMEM 65536

__global__ __launch_bounds__(256, 2)
void attn_kernel() {
    extern __shared__ char smc[];
    const uint32_t sQ = smem_u32(smc);

    const int bh = blockIdx.y;
    const int qt = 15 - (int)blockIdx.x;
    const int q0 = qt * 128;
    const int t  = threadIdx.x;
    const int w  = t >> 5;
    const int lid = t & 31;

    const __nv_bfloat16* Qg  = g_qb  + (size_t)bh * S_LEN * HDIM;
    const __nv_bfloat16* Kg  = g_kb  + (size_t)bh * S_LEN * HDIM;
    const __nv_bfloat16* Vhg = g_vhb + (size_t)bh * S_LEN * HDIM;
    const __nv_bfloat16* Vlg = g_vlb + (size_t)bh * S_LEN * HDIM;

    {
        const int row = t >> 1;
        const int half = (t & 1) * 64;
        const char* src = (const char*)(Qg + (size_t)(q0 + row) * HDIM) + half;
#pragma unroll
        for (int i = 0; i < 4; ++i)
            cp16(sQ + sw128((uint32_t)row * 128u + half + i * 16), src + i * 16);
    }
    {
        const int row = t >> 2;
        const int qo = (t & 3) * 32;
        const uint32_t so = sw128((uint32_t)row * 128u + qo);
        const uint32_t so2 = sw128((uint32_t)row * 128u + qo + 16);
        const char* kg = (const char*)(Kg + (size_t)row * HDIM) + qo;
        const char* vh = (const char*)(Vhg + (size_t)row * HDIM) + qo;
        const char* vl = (const char*)(Vlg + (size_t)row * HDIM) + qo;
        uint32_t bK = sQ + 16384u;
        cp16(bK + so, kg);           cp16(bK + so2, kg + 16);
        cp16(bK + 8192u + so, vh);   cp16(bK + 8192u + so2, vh + 16);
        cp16(bK + 16384u + so, vl);  cp16(bK + 16384u + so2, vl + 16);
    }
    cp_commit();

    float oc[8][4];
#pragma unroll
    for (int jn = 0; jn < 8; ++jn)
#pragma unroll
        for (int q = 0; q < 4; ++q) oc[jn][q] = 0.0f;
    float m[2] = {-1e30f, -1e30f};
    float l[2] = {0.0f, 0.0f};

    const int nkt = 2 * qt + 2;
#pragma unroll 1
    for (int kt = 0; kt < nkt; ++kt) {
        if (kt + 1 < nkt) {
            const int k1 = (kt + 1) * 64;
            const int row = t >> 2;
            const int qo = (t & 3) * 32;
            const uint32_t so = sw128((uint32_t)row * 128u + qo);
            const uint32_t so2 = sw128((uint32_t)row * 128u + qo + 16);
            const char* kg = (const char*)(Kg + (size_t)(k1 + row) * HDIM) + qo;
            const char* vh = (const char*)(Vhg + (size_t)(k1 + row) * HDIM) + qo;
            const char* vl = (const char*)(Vlg + (size_t)(k1 + row) * HDIM) + qo;
            uint32_t bK = sQ + 16384u + ((kt + 1) & 1) * 24576u;
            cp16(bK + so, kg);           cp16(bK + so2, kg + 16);
            cp16(bK + 8192u + so, vh);   cp16(bK + 8192u + so2, vh + 16);
            cp16(bK + 16384u + so, vl);  cp16(bK + 16384u + so2, vl + 16);
            cp_commit();
            asm volatile("cp.async.wait_group 1;" ::: "memory");
        } else {
            asm volatile("cp.async.wait_group 0;" ::: "memory");
        }
        __syncthreads();

        const uint32_t bK  = sQ + 16384u + (kt & 1) * 24576u;
        const uint32_t bVh = bK + 8192u;
        const uint32_t bVl = bK + 16384u;
        const int k0 = kt * 64;

        float sc[8][4];
#pragma unroll
        for (int jn = 0; jn < 8; ++jn)
#pragma unroll
            for (int q = 0; q < 4; ++q) sc[jn][q] = 0.0f;

#pragma unroll
        for (int k4 = 0; k4 < 4; ++k4) {
            uint32_t QA[4];
            LDSM4(QA, sQ + sw128((uint32_t)(w * 16 + (lid & 15)) * 128u + k4 * 32 + (lid >> 4) * 16));
#pragma unroll
            for (int j2 = 0; j2 < 4; ++j2) {
                uint32_t KB[4];
                LDSM4(KB, bK + sw128((uint32_t)((lid & 7) + ((lid >> 4) << 3) + j2 * 16) * 128u
                                     + k4 * 32 + ((lid >> 3) & 1) * 16));
                mma_bf16(sc[j2 * 2 + 0], QA, KB[0], KB[1]);
                mma_bf16(sc[j2 * 2 + 1], QA, KB[2], KB[3]);
            }
        }

        if (k0 + 63 > q0 + w * 16) {
            const int rlo = q0 + w * 16 + (lid >> 2);
#pragma unroll
            for (int jn = 0; jn < 8; ++jn) {
                const int cb = k0 + jn * 8 + (lid & 3) * 2;
#pragma unroll
                for (int q = 0; q < 4; ++q) {
                    const int colg = cb + (q & 1);
                    const int rowg = rlo + (q >> 1) * 8;
                    if (colg > rowg) sc[jn][q] += MASK_NEG;
                }
            }
        }

#pragma unroll
        for (int hh = 0; hh < 2; ++hh) {
            float mt = sc[0][hh * 2];
#pragma unroll
            for (int jn = 0; jn < 8; ++jn)
                mt = fmaxf(mt, fmaxf(sc[jn][hh * 2], sc[jn][hh * 2 + 1]));
            mt = fmaxf(mt, __shfl_xor_sync(0xffffffffu, mt, 1));
            mt = fmaxf(mt, __shfl_xor_sync(0xffffffffu, mt, 2));

            const float mn = fmaxf(m[hh], mt);
            const float corr = __expf(m[hh] - mn);
            float ps = 0.0f;
#pragma unroll
            for (int jn = 0; jn < 8; ++jn) {
                float p0 = __expf(sc[jn][hh * 2] - mn);
                float p1 = __expf(sc[jn][hh * 2 + 1] - mn);
                sc[jn][hh * 2] = p0;
                sc[jn][hh * 2 + 1] = p1;
                ps += p0 + p1;
            }
            ps += __shfl_xor_sync(0xffffffffu, ps, 1);
            ps += __shfl_xor_sync(0xffffffffu, ps, 2);
            l[hh] = l[hh] * corr + ps;
            m[hh] = mn;
#pragma unroll
            for (int jn = 0; jn < 8; ++jn) {
                oc[jn][hh * 2] *= corr;
                oc[jn][hh * 2 + 1] *= corr;
            }
        }

#pragma unroll
        for (int k4 = 0; k4 < 4; ++k4) {
            uint32_t PhA[4], PlA[4];
            {
                float r0, r1, r2, r3, r4, r5, r6, r7;
                PhA[0] = packlo(sc[2 * k4][0], sc[2 * k4][1], r0, r1);
                PhA[1] = packlo(sc[2 * k4][2], sc[2 * k4][3], r2, r3);
                PhA[2] = packlo(sc[2 * k4 + 1][0], sc[2 * k4 + 1][1], r4, r5);
                PhA[3] = packlo(sc[2 * k4 + 1][2], sc[2 * k4 + 1][3], r6, r7);
                PlA[0] = packb(r0, r1);
                PlA[1] = packb(r2, r3);
                PlA[2] = packb(r4, r5);
                PlA[3] = packb(r6, r7);
            }
#pragma unroll
            for (int j2 = 0; j2 < 4; ++j2) {
                uint32_t VhB[4], VlB[4];
                LDSM4T(VhB, bVh + sw128((uint32_t)(k4 * 16 + (lid & 15)) * 128u + j2 * 32 + (lid >> 4) * 16));
                LDSM4T(VlB, bVl + sw128((uint32_t)(k4 * 16 + (lid & 15)) * 128u + j2 * 32 + (lid >> 4) * 16));
                mma_bf16(oc[j2 * 2 + 0], PhA, VhB[0], VhB[1]);
                mma_bf16(oc[j2 * 2 + 1], PhA, VhB[2], VhB[3]);
                mma_bf16(oc[j2 * 2 + 0], PhA, VlB[0], VlB[1]);
                mma_bf16(oc[j2 * 2 + 1], PhA, VlB[2], VlB[3]);
                mma_bf16(oc[j2 * 2 + 0], PlA, VhB[0], VhB[1]);
                mma_bf16(oc[j2 * 2 + 1], PlA, VhB[2], VhB[3]);
            }
        }
        __syncthreads();
    }

    const int b = bh >> 5;
    const int h = bh & 31;
#pragma unroll
    for (int hh = 0; hh < 2; ++hh) {
        const int row = q0 + w * 16 + (lid >> 2) + hh * 8;
        const float invl = 1.0f / l[hh];
        float* dst = g_ctx + (size_t)(row * BATCH + b) * EMB + h * HDIM;
#pragma unroll
        for (int jn = 0; jn < 8; ++jn) {
            float2 v = make_float2(oc[jn][hh * 2] * invl, oc[jn][hh * 2 + 1] * invl);
            *reinterpret_cast<float2*>(dst + jn * 8 + (lid & 3) * 2) = v;
        }
    }
}

// ---------------------------------------------------------------------------
// Launch
// ---------------------------------------------------------------------------
extern "C" void kernel_launch(void* const* d_in, const int* in_sizes, int n_in,
                              void* d_out, int out_size) {
    const float* hs    = (const float*)d_in[0];
    const float* qkv_w = (const float*)d_in[1];
    const float* qkv_b = (const float*)d_in[2];
    const float* out_w = (const float*)d_in[3];
    const float* out_b = (const float*)d_in[4];
    float* out = (float*)d_out;

    cudaFuncSetAttribute(gemm_mma_tf32, cudaFuncAttributeMaxDynamicSharedMemorySize, GEMM_SMEM);
    cudaFuncSetAttribute(attn_kernel, cudaFuncAttributeMaxDynamicSharedMemorySize, ATTN_SMEM);

    float *qkv, *ctx, *Btq, *Bto;
    cudaGetSymbolAddress((void**)&qkv, g_qkv);
    cudaGetSymbolAddress((void**)&ctx, g_ctx);
    cudaGetSymbolAddress((void**)&Btq, g_Btq);
    cudaGetSymbolAddress((void**)&Bto, g_Bto);

    // Weight transposes (fp32; operands consumed as tf32 by the MMA)
    {
        dim3 blk(32, 32);
        transpose_kernel<<<dim3(QKV_N / 32, KDIM / 32), blk>>>(qkv_w, Btq, QKV_N);
        transpose_kernel<<<dim3(EMB / 32, KDIM / 32), blk>>>(out_w, Bto, EMB);
    }

    // 1. QKV projection (TF32 MMA, A = hs directly)
    gemm_mma_tf32<<<dim3(QKV_N / 128, MROWS / 128), 256, GEMM_SMEM>>>(QKV_N, hs, Btq, qkv_b, qkv);

    // 2. RoPE + split -> bf16 Q/K/Vh/Vl
    rope_split_kernel<<<(S_LEN * BATCH * HEADS * HDIM) / 256, 256>>>();

    // 3. Causal attention (HMMA flash)
    attn_kernel<<<dim3(S_LEN / 128, BATCH * HEADS), 256, ATTN_SMEM>>>();

    // 4. Output projection (TF32 MMA, A = ctx directly)
    gemm_mma_tf32<<<dim3(EMB / 128, MROWS / 128), 256, GEMM_SMEM>>>(EMB, ctx, Bto, out_b, out);
}